// round 4
// baseline (speedup 1.0000x reference)
#include <cuda_runtime.h>
#include <cstdint>

typedef unsigned long long u64;

#define NB 8
#define NT 1024
#define NS 64
#define DM 256
#define DH 128

// scratch: s_proj[b][n][h]  (8*64*128 floats = 256KB)
__device__ float g_sproj[NB * NS * DH];

// ---------------- packed f32x2 helpers ----------------
__device__ __forceinline__ u64 pk_fma(u64 acc, u64 a, u64 b) {
    asm("fma.rn.f32x2 %0, %1, %2, %0;" : "+l"(acc) : "l"(a), "l"(b));
    return acc;
}

// acc += relu(f2 + s2) * w2   (packed pair; relu via scalar max on halves)
__device__ __forceinline__ u64 relu_fma2(u64 acc, u64 f2, u64 s2, u64 w2) {
    asm("{\n\t"
        ".reg .b64 t;\n\t"
        ".reg .f32 lo, hi;\n\t"
        "add.rn.f32x2 t, %1, %2;\n\t"
        "mov.b64 {lo, hi}, t;\n\t"
        "max.f32 lo, lo, 0f00000000;\n\t"
        "max.f32 hi, hi, 0f00000000;\n\t"
        "mov.b64 t, {lo, hi};\n\t"
        "fma.rn.f32x2 %0, t, %3, %0;\n\t"
        "}"
        : "+l"(acc) : "l"(f2), "l"(s2), "l"(w2));
    return acc;
}

__device__ __forceinline__ float pk_sum(u64 a) {
    return __uint_as_float((unsigned)a) + __uint_as_float((unsigned)(a >> 32));
}

// ---------------- kernel 1: s_proj = slots @ W_s + b_proj ----------------
// 64 CTAs x 256 threads; 8 slot-rows per CTA. Whole W_s staged ONCE per CTA
// into smem (transposed, pitch 258 -> conflict-free LDS.64), killing the
// 64MB redundant L2 traffic of the per-row version.
#define SP_PITCH 258
#define SP_W_FLOATS (DH * SP_PITCH)               // 33024
#define SP_SMEM_FLOATS (SP_W_FLOATS + 8 * DM)     // + 8 slot rows
#define SP_SMEM_BYTES (SP_SMEM_FLOATS * 4)        // 140,288 B

__global__ void __launch_bounds__(256) sproj_kernel(
    const float* __restrict__ slots, const float* __restrict__ W_proj,
    const float* __restrict__ b_proj)
{
    extern __shared__ float sm[];
    float* wS = sm;                 // [h][k] transposed W_s, pitch 258
    float* sl = sm + SP_W_FLOATS;   // 8 x 256 slot rows
    const int tid = threadIdx.x;

    // stage W_s transposed as k-pairs (STS.64, bank = (h + k2) mod 32 -> clean)
#pragma unroll 8
    for (int q = 0; q < 64; q++) {
        int fid = tid + (q << 8);
        int h = fid & 127, k2 = fid >> 7;           // k2: 0..127
        float lo = W_proj[(DM + 2 * k2) * DH + h];
        float hi = W_proj[(DM + 2 * k2 + 1) * DH + h];
        *(float2*)&wS[h * SP_PITCH + 2 * k2] = make_float2(lo, hi);
    }
    // stage 8 slot rows
    const float* sg = slots + (size_t)blockIdx.x * 8 * DM;
#pragma unroll
    for (int q = 0; q < 8; q++) {
        int fid = tid + (q << 8);
        sl[fid] = sg[fid];
    }
    __syncthreads();

    const int h = tid & 127;
    const int rg = tid >> 7;        // 0..1 -> 4 rows each
    u64 acc[4] = {0ull, 0ull, 0ull, 0ull};
#pragma unroll 8
    for (int k2 = 0; k2 < 128; k2++) {
        u64 w2 = *(const u64*)&wS[h * SP_PITCH + 2 * k2];
#pragma unroll
        for (int i = 0; i < 4; i++) {
            u64 s2 = *(const u64*)&sl[(rg * 4 + i) * DM + 2 * k2];
            acc[i] = pk_fma(acc[i], s2, w2);
        }
    }
    const float bp = b_proj[h];
#pragma unroll
    for (int i = 0; i < 4; i++) {
        int row = blockIdx.x * 8 + rg * 4 + i;      // 0..511 = b*64+n
        g_sproj[row * DH + h] = pk_sum(acc[i]) + bp;
    }
}

// ---------------- kernel 2: fused f_proj GEMM + relu-head ----------------
// t-tile 32, grid 256 (fills all 148 SMs, ~2 CTAs/SM), 256 threads,
// thread-tile 4x4, smem regions aliased to 50.4KB.
#define PA 68                         // aS pitch
#define B_OFF 2176                    // bS after aS (32*68)
#define PF 130                        // f/s tile pitch
#define FS_OFF 0                      // fS aliases aS/bS region (after sync)
#define WS_OFF 4160                   // after fS (32*130)
#define SS_OFF 4288                   // after wS (128)
#define SMEM_FLOATS 12608             // SS_OFF + 64*130
#define SMEM_BYTES (SMEM_FLOATS * 4)  // 50,432 B

__global__ void __launch_bounds__(256) main_kernel(
    const float* __restrict__ features, const float* __restrict__ W_proj,
    const float* __restrict__ w_head, const float* __restrict__ b_head,
    float* __restrict__ out)
{
    extern __shared__ float sm[];
    const int tid = threadIdx.x;
    const int b  = blockIdx.x >> 5;          // 0..7
    const int t0 = (blockIdx.x & 31) << 5;   // 0,32,...,992
    const int mq = tid >> 5;                 // 0..7  (uniform per warp)
    const int nq = tid & 31;                 // 0..31 (lane)

    float* aS = sm;                          // 32 x 68
    float* bS = sm + B_OFF;                  // 128 x 64 (pair-swizzled)

    // ======== Phase 1: f[32][128] = features[b, t0:t0+32, :] @ W_f ========
    u64 acc[4][4];
#pragma unroll
    for (int i = 0; i < 4; i++)
#pragma unroll
        for (int j = 0; j < 4; j++) acc[i][j] = 0ull;

    for (int kc = 0; kc < 4; kc++) {
        const int k0 = kc << 6;
        __syncthreads();
        // stage A: 32 rows x 64 k (coalesced)
#pragma unroll
        for (int q = 0; q < 8; q++) {
            int fid = tid + (q << 8);
            int m = fid >> 6, k = fid & 63;
            aS[m * PA + k] = features[((size_t)(b * NT + t0 + m)) * DM + k0 + k];
        }
        // stage B as k-pairs: (k2,h) -> bS[h*64 + 2*(k2 ^ (h&31))]
        // STS.64 banks = (k2 ^ lane) mod 32 -> conflict-free
#pragma unroll
        for (int q = 0; q < 16; q++) {
            int fid = tid + (q << 8);
            int h = fid & 127, k2 = fid >> 7;        // k2: 0..31
            int kg = k0 + (k2 << 1);
            float lo = W_proj[kg * DH + h];
            float hi = W_proj[(kg + 1) * DH + h];
            *(float2*)&bS[(h << 6) + 2 * (k2 ^ (h & 31))] = make_float2(lo, hi);
        }
        __syncthreads();
#pragma unroll 8
        for (int k2 = 0; k2 < 32; k2++) {
            u64 a2[4], b2[4];
#pragma unroll
            for (int i = 0; i < 4; i++)              // broadcast (mq uniform)
                a2[i] = *(const u64*)&aS[(mq + (i << 3)) * PA + (k2 << 1)];
            const int swz = 2 * (k2 ^ nq);           // h&31 == nq for all j
#pragma unroll
            for (int j = 0; j < 4; j++)              // 32 distinct banks
                b2[j] = *(const u64*)&bS[((nq + (j << 5)) << 6) + swz];
#pragma unroll
            for (int i = 0; i < 4; i++)
#pragma unroll
                for (int j = 0; j < 4; j++)
                    acc[i][j] = pk_fma(acc[i][j], a2[i], b2[j]);
        }
    }
    __syncthreads();   // all aS/bS reads done before region reuse

    // write f tile (scalar = lo + hi of k-packed acc), stage s tile + w
    float* fS = sm + FS_OFF;
    float* wS = sm + WS_OFF;
    float* sS = sm + SS_OFF;
#pragma unroll
    for (int i = 0; i < 4; i++)
#pragma unroll
        for (int j = 0; j < 4; j++)
            fS[(mq + (i << 3)) * PF + nq + (j << 5)] = pk_sum(acc[i][j]);
    {
        const float* gsp = g_sproj + b * (NS * DH);
#pragma unroll
        for (int q = 0; q < 32; q++) {
            int fid = tid + (q << 8);
            int n = fid >> 7, h = fid & 127;
            sS[n * PF + h] = gsp[fid];
        }
        if (tid < DH) wS[tid] = w_head[tid];
    }
    __syncthreads();

    // ======== Phase 2: out[t,n] = sum_h relu(f[t,h]+s[n,h])*w[h] + b ========
    u64 acc2[4][2];
#pragma unroll
    for (int i = 0; i < 4; i++)
#pragma unroll
        for (int j = 0; j < 2; j++) acc2[i][j] = 0ull;

#pragma unroll 8
    for (int h2 = 0; h2 < 64; h2++) {
        u64 w2 = *(const u64*)&wS[h2 << 1];
        u64 f2[4], s2[2];
#pragma unroll
        for (int i = 0; i < 4; i++)                  // broadcast
            f2[i] = *(const u64*)&fS[(mq + (i << 3)) * PF + (h2 << 1)];
#pragma unroll
        for (int j = 0; j < 2; j++)                  // banks (nq+h2)%32
            s2[j] = *(const u64*)&sS[(nq + (j << 5)) * PF + (h2 << 1)];
#pragma unroll
        for (int i = 0; i < 4; i++)
#pragma unroll
            for (int j = 0; j < 2; j++)
                acc2[i][j] = relu_fma2(acc2[i][j], f2[i], s2[j], w2);
    }

    const float bh = b_head[0];
    float* ob = out + ((size_t)(b * NT + t0)) * NS;
#pragma unroll
    for (int i = 0; i < 4; i++)
#pragma unroll
        for (int j = 0; j < 2; j++)
            ob[(mq + (i << 3)) * NS + nq + (j << 5)] = pk_sum(acc2[i][j]) + bh;
}

// ---------------- launch ----------------
extern "C" void kernel_launch(void* const* d_in, const int* in_sizes, int n_in,
                              void* d_out, int out_size)
{
    const float* features = (const float*)d_in[0];   // (8,1024,256)
    const float* slots    = (const float*)d_in[1];   // (8,64,256)
    const float* W_proj   = (const float*)d_in[2];   // (512,128)
    const float* b_proj   = (const float*)d_in[3];   // (128,)
    const float* w_head   = (const float*)d_in[4];   // (128,)
    const float* b_head   = (const float*)d_in[5];   // ()
    float* out = (float*)d_out;                      // (8,1024,64)

    (void)in_sizes; (void)n_in; (void)out_size;

    cudaFuncSetAttribute(sproj_kernel, cudaFuncAttributeMaxDynamicSharedMemorySize, SP_SMEM_BYTES);
    cudaFuncSetAttribute(main_kernel,  cudaFuncAttributeMaxDynamicSharedMemorySize, SMEM_BYTES);

    sproj_kernel<<<64, 256, SP_SMEM_BYTES>>>(slots, W_proj, b_proj);
    main_kernel<<<NB * (NT / 32), 256, SMEM_BYTES>>>(features, W_proj, w_head, b_head, out);
}

// round 6
// speedup vs baseline: 1.5420x; 1.5420x over previous
#include <cuda_runtime.h>
#include <cstdint>

typedef unsigned long long u64;

#define NB 8
#define NT 1024
#define NS 64
#define DM 256
#define DH 128

// scratch: s_proj[b][n][h]  (8*64*128 floats = 256KB)
__device__ float g_sproj[NB * NS * DH];

// ---------------- packed f32x2 helpers ----------------
__device__ __forceinline__ u64 pk_fma(u64 acc, u64 a, u64 b) {
    asm("fma.rn.f32x2 %0, %1, %2, %0;" : "+l"(acc) : "l"(a), "l"(b));
    return acc;
}

// acc += relu(f2 + s2) * w2
__device__ __forceinline__ u64 relu_fma2(u64 acc, u64 f2, u64 s2, u64 w2) {
    asm("{\n\t"
        ".reg .b64 t;\n\t"
        ".reg .f32 lo, hi;\n\t"
        "add.rn.f32x2 t, %1, %2;\n\t"
        "mov.b64 {lo, hi}, t;\n\t"
        "max.f32 lo, lo, 0f00000000;\n\t"
        "max.f32 hi, hi, 0f00000000;\n\t"
        "mov.b64 t, {lo, hi};\n\t"
        "fma.rn.f32x2 %0, t, %3, %0;\n\t"
        "}"
        : "+l"(acc) : "l"(f2), "l"(s2), "l"(w2));
    return acc;
}

__device__ __forceinline__ float pk_sum(u64 a) {
    return __uint_as_float((unsigned)a) + __uint_as_float((unsigned)(a >> 32));
}

// pair-block swizzle position for k2 within a 64-float row of h/n:
// 16B block index x = (k2>>1) ^ ((h>>1)&15); even k2 pair at +0, odd at +2.
__device__ __forceinline__ int bswz(int k2, int h) {
    return 4 * ((k2 >> 1) ^ ((h >> 1) & 15)) + 2 * (k2 & 1);
}

// ---------------- kernel 1: s_proj = slots @ W_s + b_proj ----------------
// 64 CTAs x 256 thr; 8 rows/CTA; W_s staged in 32KB chunks (64k x 128h),
// pair-swizzled for conflict-free LDS.128.
__global__ void __launch_bounds__(256) sproj_kernel(
    const float* __restrict__ slots, const float* __restrict__ W_proj,
    const float* __restrict__ b_proj)
{
    __shared__ __align__(16) float wS[DH * 64];   // 8192 floats (one k-chunk)
    __shared__ __align__(16) float sl[8 * DM];    // 8 slot rows

    const int tid = threadIdx.x;
    const int h  = tid & 127;
    const int rg = tid >> 7;                      // 0..1 -> 4 rows each

    // stage 8 slot rows once
    const float* sg = slots + (size_t)blockIdx.x * 8 * DM;
#pragma unroll
    for (int q = 0; q < 8; q++) sl[tid + (q << 8)] = sg[tid + (q << 8)];

    u64 acc[4] = {0ull, 0ull, 0ull, 0ull};

    for (int kc = 0; kc < 4; kc++) {
        const int k0 = kc << 6;
        __syncthreads();
        // stage W_s chunk transposed + pair-swizzled (4096 pairs / 256 thr)
#pragma unroll
        for (int q = 0; q < 16; q++) {
            int fid = tid + (q << 8);
            int hh = fid & 127, k2 = fid >> 7;    // k2 0..31
            float lo = W_proj[(DM + k0 + 2 * k2) * DH + hh];
            float hi = W_proj[(DM + k0 + 2 * k2 + 1) * DH + hh];
            *(float2*)&wS[(hh << 6) + bswz(k2, hh)] = make_float2(lo, hi);
        }
        __syncthreads();
#pragma unroll
        for (int q2 = 0; q2 < 16; q2++) {
            ulonglong2 w4 = *(const ulonglong2*)&wS[(h << 6) + 4 * (q2 ^ ((h >> 1) & 15))];
#pragma unroll
            for (int i = 0; i < 4; i++) {
                ulonglong2 s4 = *(const ulonglong2*)&sl[(rg * 4 + i) * DM + k0 + (q2 << 2)];
                acc[i] = pk_fma(acc[i], s4.x, w4.x);
                acc[i] = pk_fma(acc[i], s4.y, w4.y);
            }
        }
    }
    const float bp = b_proj[h];
#pragma unroll
    for (int i = 0; i < 4; i++) {
        int row = blockIdx.x * 8 + rg * 4 + i;
        g_sproj[row * DH + h] = pk_sum(acc[i]) + bp;
    }
}

// ---------------- kernel 2: fused f_proj GEMM + relu-head ----------------
// 64-t tile, grid 128, 512 threads (16 warps/SM), thread tile 8m x 2n,
// all operands via conflict-free LDS.128.
#define PA 68                          // aS pitch (mult of 4)
#define B_OFF 4352                     // bS after aS (64*68)
#define PF 132                         // f/s pitch (mult of 4)
#define FS_OFF 0                       // fS aliases phase-1 region
#define WS_OFF 8448                    // after fS (64*132)
#define SS_OFF 8576                    // after wS (128)
#define SMEM_FLOATS 17024              // SS_OFF + 64*132
#define SMEM_BYTES (SMEM_FLOATS * 4)   // 68,096 B

__global__ void __launch_bounds__(512) main_kernel(
    const float* __restrict__ features, const float* __restrict__ W_proj,
    const float* __restrict__ w_head, const float* __restrict__ b_head,
    float* __restrict__ out)
{
    extern __shared__ __align__(16) float sm[];
    const int tid = threadIdx.x;
    const int b  = blockIdx.x >> 4;          // 0..7
    const int t0 = (blockIdx.x & 15) << 6;   // 0..960
    const int mr = tid >> 5;                 // warp 0..15 (uniform)
    const int nq = tid & 31;                 // lane
    const int mw = (mr & 7) << 3;            // m base (8 rows per warp-group)
    const int nh = mr >> 3;                  // n half (0/1)

    float* aS = sm;                          // 64 x 68
    float* bS = sm + B_OFF;                  // 128 x 64, pair-swizzled

    // ======== Phase 1: f[64][128] = features[b, t0:, :] @ W_f ========
    u64 acc[8][2];
#pragma unroll
    for (int i = 0; i < 8; i++) { acc[i][0] = 0ull; acc[i][1] = 0ull; }

    const int swz = (nq >> 1) & 15;
    const int nb0 = nq + (nh << 5);          // n for j=0 (j=1: +64)

    for (int kc = 0; kc < 4; kc++) {
        const int k0 = kc << 6;
        __syncthreads();
        // stage A: 64 rows x 64 k (4096 floats / 512 thr)
#pragma unroll
        for (int q = 0; q < 8; q++) {
            int fid = tid + (q << 9);
            int m = fid >> 6, k = fid & 63;
            aS[m * PA + k] = features[((size_t)(b * NT + t0 + m)) * DM + k0 + k];
        }
        // stage B pair-swizzled (4096 pairs / 512 thr)
#pragma unroll
        for (int q = 0; q < 8; q++) {
            int fid = tid + (q << 9);
            int h = fid & 127, k2 = fid >> 7;  // k2 0..31
            float lo = W_proj[(k0 + 2 * k2) * DH + h];
            float hi = W_proj[(k0 + 2 * k2 + 1) * DH + h];
            *(float2*)&bS[(h << 6) + bswz(k2, h)] = make_float2(lo, hi);
        }
        __syncthreads();
#pragma unroll 4
        for (int q2 = 0; q2 < 16; q2++) {
            ulonglong2 b4[2];
#pragma unroll
            for (int j = 0; j < 2; j++)
                b4[j] = *(const ulonglong2*)&bS[((nb0 + (j << 6)) << 6) + 4 * (q2 ^ swz)];
#pragma unroll
            for (int i = 0; i < 8; i++) {
                ulonglong2 a4 = *(const ulonglong2*)&aS[(mw + i) * PA + (q2 << 2)];
#pragma unroll
                for (int j = 0; j < 2; j++) {
                    acc[i][j] = pk_fma(acc[i][j], a4.x, b4[j].x);
                    acc[i][j] = pk_fma(acc[i][j], a4.y, b4[j].y);
                }
            }
        }
    }
    __syncthreads();   // all aS/bS reads done before region reuse

    // write f tile; stage s tile + w
    float* fS = sm + FS_OFF;                 // 64 x 132
    float* wS = sm + WS_OFF;                 // 128
    float* sS = sm + SS_OFF;                 // 64 x 132
#pragma unroll
    for (int i = 0; i < 8; i++)
#pragma unroll
        for (int j = 0; j < 2; j++)
            fS[(mw + i) * PF + nb0 + (j << 6)] = pk_sum(acc[i][j]);
    {
        const float* gsp = g_sproj + b * (NS * DH);
#pragma unroll
        for (int q = 0; q < 16; q++) {
            int fid = tid + (q << 9);
            int n = fid >> 7, h = fid & 127;
            sS[n * PF + h] = gsp[fid];
        }
        if (tid < DH) wS[tid] = w_head[tid];
    }
    __syncthreads();

    // ======== Phase 2: out[t,n] = sum_h relu(f[t,h]+s[n,h])*w[h] + b ========
    // 8 outputs/thread: m = mw+i (i 0..7), n = nq + 32*nh
    const int n2 = nq + (nh << 5);
    u64 acc2[8];
#pragma unroll
    for (int i = 0; i < 8; i++) acc2[i] = 0ull;

#pragma unroll 4
    for (int q = 0; q < 32; q++) {           // q = pair of h2 (4 h values)
        ulonglong2 w4 = *(const ulonglong2*)&wS[q << 2];
        ulonglong2 s4 = *(const ulonglong2*)&sS[n2 * PF + (q << 2)];
#pragma unroll
        for (int i = 0; i < 8; i++) {
            ulonglong2 f4 = *(const ulonglong2*)&fS[(mw + i) * PF + (q << 2)];
            acc2[i] = relu_fma2(acc2[i], f4.x, s4.x, w4.x);
            acc2[i] = relu_fma2(acc2[i], f4.y, s4.y, w4.y);
        }
    }

    const float bh = b_head[0];
    float* ob = out + ((size_t)(b * NT + t0)) * NS + n2;
#pragma unroll
    for (int i = 0; i < 8; i++)
        ob[(mw + i) * NS] = pk_sum(acc2[i]) + bh;
}

// ---------------- launch ----------------
extern "C" void kernel_launch(void* const* d_in, const int* in_sizes, int n_in,
                              void* d_out, int out_size)
{
    const float* features = (const float*)d_in[0];   // (8,1024,256)
    const float* slots    = (const float*)d_in[1];   // (8,64,256)
    const float* W_proj   = (const float*)d_in[2];   // (512,128)
    const float* b_proj   = (const float*)d_in[3];   // (128,)
    const float* w_head   = (const float*)d_in[4];   // (128,)
    const float* b_head   = (const float*)d_in[5];   // ()
    float* out = (float*)d_out;                      // (8,1024,64)

    (void)in_sizes; (void)n_in; (void)out_size;

    cudaFuncSetAttribute(main_kernel, cudaFuncAttributeMaxDynamicSharedMemorySize, SMEM_BYTES);

    sproj_kernel<<<64, 256>>>(slots, W_proj, b_proj);
    main_kernel<<<NB * (NT / 64), 512, SMEM_BYTES>>>(features, W_proj, w_head, b_head, out);
}